// round 17
// baseline (speedup 1.0000x reference)
#include <cuda_runtime.h>
#include <cstdint>

// ---------------------------------------------------------------------------
// CVQNN classifier: out[b,w] = log1p(relu(c0[w] + mx'^2 + mp'^2))
//   mx'[w] = sum_k A[k][w]   *x[b,k] + bias[w]     (A = S[rows,:64], bias=d/2)
//   mp'[w] = sum_k A[k][10+w]*x[b,k] + bias[10+w]
// Three graph nodes: setup kernel (row-backward, writes g_blob) ->
// cudaMemcpyToSymbolAsync(g_blob -> c_blob, D2D) -> main kernel.
// A/bias/c0 are read through the CONSTANT port (ld.const), off the L1tex
// pipe that was binding at 71%. Main kernel: 128 thr, 2 rows/thr, 256-row
// tile, 2 warp-private quarter buffers (occ 5), per-warp cp.async waits,
// ZERO block barriers anywhere in the main kernel.
// ---------------------------------------------------------------------------

// layout (float idx): [0,1280) A[k][o] (k*20+o); [1280,1300) bias; [1300,1310) c0
__device__   __align__(16) float     g_blob[1312];
__constant__ __align__(16) longlong2 c_blob[328];   // same bytes, ll2 view

// ---------------- f32x2 packed-math helpers --------------------------------
#define FMA2(acc, a, b) \
    asm("fma.rn.f32x2 %0, %1, %2, %0;" : "+l"(acc) : "l"(a), "l"(b))
#define MUL2(d, a, b) \
    asm("mul.rn.f32x2 %0, %1, %2;" : "=l"(d) : "l"(a), "l"(b))
#define ADD2(d, a, b) \
    asm("add.rn.f32x2 %0, %1, %2;" : "=l"(d) : "l"(a), "l"(b))
#define PACK_DUP(d, f) \
    asm("mov.b64 %0, {%1, %1};" : "=l"(d) : "f"(f))
#define UNPACK2(lo, hi, v) \
    asm("mov.b64 {%0, %1}, %2;" : "=f"(lo), "=f"(hi) : "l"(v))

// ---------------------------------------------------------------------------
// Setup kernel (1 block, 128 threads): row-backward propagation v^T <- v^T*F.
// ---------------------------------------------------------------------------

__device__ __forceinline__ void bs_back(float v[20], float* sv,
                                        const float* p, int start, int tid) {
    const int m = tid & 63;
    const bool lower = tid < 64;
    const bool active = (m >= start) && (m < start + ((start == 0) ? 64 : 62));
#pragma unroll
    for (int w = 0; w < 20; ++w) sv[w * 132 + tid] = v[w];
    __syncthreads();
    if (active) {
        const int rel = m - start;
        const int i = start + (rel & ~1);
        const bool is_i = (rel & 1) == 0;
        float st_, ct_, sp_, cp_;
        __sincosf(p[3 * i], &st_, &ct_);
        __sincosf(p[3 * i + 1], &sp_, &cp_);
        const int o = is_i ? (i + 1) : i;
        const int sameIdx = (lower ? 0 : 64) + o;
        const int crossIdx = (lower ? 64 : 0) + o;
        const float cA1 = (is_i ? cp_ : -cp_) * st_;
        const float cA2 = (lower ? sp_ : -sp_) * st_;
#pragma unroll
        for (int w = 0; w < 20; ++w)
            v[w] = ct_ * v[w] + cA1 * sv[w * 132 + sameIdx]
                              + cA2 * sv[w * 132 + crossIdx];
    }
    __syncthreads();
}

__device__ __forceinline__ void r_back(float v[20], float* sv,
                                       const float* p, int tid) {
    const int k = tid & 63;
    const bool lower = tid < 64;
    float c_ = 1.0f, s_ = 0.0f;
    if (k < 63) __sincosf(p[3 * k + 2], &s_, &c_);
#pragma unroll
    for (int w = 0; w < 20; ++w) sv[w * 132 + tid] = v[w];
    __syncthreads();
    const float cs = lower ? s_ : -s_;
    const int cross = tid ^ 64;
#pragma unroll
    for (int w = 0; w < 20; ++w)
        v[w] = c_ * v[w] + cs * sv[w * 132 + cross];
    __syncthreads();
}

__global__ __launch_bounds__(128, 1) void setup_kernel(
    const float* __restrict__ i1_0, const float* __restrict__ sq0,
    const float* __restrict__ i2_0, const float* __restrict__ d0,
    const float* __restrict__ i1_1, const float* __restrict__ sq1,
    const float* __restrict__ i2_1, const float* __restrict__ d1) {
    __shared__ float sv[2660];
    const int tid = threadIdx.x;
    const int k = tid & 63;
    const bool lower = tid < 64;
    float v[20];
#pragma unroll
    for (int w = 0; w < 20; ++w) {
        const int r = (w < 10) ? w : (54 + w);  // rows = [0..9, 64..73]
        v[w] = (tid == r) ? 1.0f : 0.0f;
    }
    // ---- layer 1 (leftmost in S) ----
    bs_back(v, sv, i2_1, 1, tid);
    bs_back(v, sv, i2_1, 0, tid);
    {
        const float e = lower ? __expf(-sq1[k]) : __expf(sq1[k]);
#pragma unroll
        for (int w = 0; w < 20; ++w) v[w] *= e;
    }
    r_back(v, sv, i1_1, tid);
    bs_back(v, sv, i1_1, 1, tid);
    bs_back(v, sv, i1_1, 0, tid);
    // dot0 = row_r(M_L1) . [2*disp0; 0]
#pragma unroll
    for (int w = 0; w < 20; ++w)
        sv[w * 132 + tid] = lower ? v[w] * 2.0f * d0[tid] : 0.0f;
    __syncthreads();
    if (tid < 20) {
        float s = 0.0f;
        for (int t = 0; t < 64; ++t) s += sv[tid * 132 + t];
        sv[2640 + tid] = s;
    }
    __syncthreads();
    // ---- layer 0 ----
    bs_back(v, sv, i2_0, 1, tid);
    bs_back(v, sv, i2_0, 0, tid);
    {
        const float e = lower ? __expf(-sq0[k]) : __expf(sq0[k]);
#pragma unroll
        for (int w = 0; w < 20; ++w) v[w] *= e;
    }
    r_back(v, sv, i1_0, tid);
    bs_back(v, sv, i1_0, 1, tid);
    bs_back(v, sv, i1_0, 0, tid);
    // ---- outputs into g_blob ----
    if (lower) {
#pragma unroll
        for (int o = 0; o < 20; ++o) g_blob[tid * 20 + o] = v[o];
    }
#pragma unroll
    for (int w = 0; w < 10; ++w)
        sv[w * 132 + tid] = v[w] * v[w] + v[w + 10] * v[w + 10];
    __syncthreads();
    if (tid < 10) {
        float s = 0.0f;
        for (int t = 0; t < 128; ++t) s += sv[tid * 132 + t];
        g_blob[1300 + tid] = 0.25f * s - 0.5f;         // c0
    }
    if (tid < 20) {
        float b = 0.5f * sv[2640 + tid];
        if (tid < 10) b += d1[tid];
        g_blob[1280 + tid] = b;                        // bias
    }
}

// ---------------------------------------------------------------------------
// Main: 128 threads, 2 rows/thread, 256-row tile, 2 quarter buffers (occ 5).
// smem: 2 buffers of 256 rows x 4 float4 (16 KB each). A via ld.const.
// Swizzle: f4i = (row<<2) + (q ^ ((row>>1)&3))  -> conflict-free LDS.128.
// Warp w stages+computes rows {e*128 + w*32 + lane}: per-warp sync only.
// ---------------------------------------------------------------------------

#define QBUF       4096                     // floats per quarter buffer
#define SMEM_BYTES (2 * QBUF * 4)

#define CP_COMMIT() asm volatile("cp.async.commit_group;" ::: "memory")
#define CP_WAIT(N)  asm volatile("cp.async.wait_group %0;" :: "n"(N) : "memory")

// stage this warp's 64 rows of k-quarter QH into buffer BUF (8 x 16B/thread)
#define STAGEW(QH, BUF)                                                       \
    do {                                                                      \
        _Pragma("unroll")                                                     \
        for (int it = 0; it < 8; ++it) {                                      \
            const int flat = (it << 5) + lane;   /* 0..255 */                 \
            const int sr = flat >> 2, q = flat & 3;                           \
            const int rloc = (wid << 5) + sr + ((sr >> 5) * 96);              \
            int grow = base + rloc;                                           \
            if (grow > Bm1) grow = Bm1;                                       \
            const int f4i = (rloc << 2) + (q ^ ((rloc >> 1) & 3));            \
            const unsigned sa = sbase +                                       \
                                (BUF) * (QBUF * 4u) + (unsigned)f4i * 16u;    \
            const float4* gp = x4 + (size_t)grow * 16 + (QH) * 4 + q;         \
            asm volatile("cp.async.cg.shared.global [%0], [%1], 16;"          \
                         :: "r"(sa), "l"(gp) : "memory");                     \
        }                                                                     \
        CP_COMMIT();                                                          \
    } while (0)

// consume k-quarter QH from buffer BUF: 16 k x 2 rows x 10 FFMA2.
// A operands come from the CONSTANT bank (separate port, off L1tex).
#define COMPUTE(QH, BUF)                                                      \
    do {                                                                      \
        const float4* s4 =                                                    \
            reinterpret_cast<const float4*>(sx + (BUF) * QBUF);               \
        _Pragma("unroll")                                                     \
        for (int kk = 0; kk < 4; ++kk) {                                      \
            float4 xv[2];                                                     \
            _Pragma("unroll")                                                 \
            for (int e = 0; e < 2; ++e)                                       \
                xv[e] = s4[(((e << 7) + tid) << 2) + (kk ^ sw)];              \
            _Pragma("unroll")                                                 \
            for (int q = 0; q < 4; ++q) {                                     \
                const int k = (QH) * 16 + kk * 4 + q;                         \
                long long a[10];                                              \
                _Pragma("unroll")                                             \
                for (int j = 0; j < 5; ++j) {                                 \
                    const longlong2 vv = c_blob[k * 5 + j];                   \
                    a[2 * j] = vv.x;                                          \
                    a[2 * j + 1] = vv.y;                                      \
                }                                                             \
                _Pragma("unroll")                                             \
                for (int e = 0; e < 2; ++e) {                                 \
                    const float xk = reinterpret_cast<const float*>(&xv[e])[q]; \
                    long long xx;                                             \
                    PACK_DUP(xx, xk);                                         \
                    _Pragma("unroll")                                         \
                    for (int p = 0; p < 10; ++p) FMA2(acc[e][p], a[p], xx);   \
                }                                                             \
            }                                                                 \
        }                                                                     \
    } while (0)

__global__ __launch_bounds__(128, 5) void cvqnn_main(
    const float* __restrict__ x, float* __restrict__ out, int B) {
    extern __shared__ float sx[];  // [b0 4096f][b1 4096f]
    const int tid = threadIdx.x;
    const int lane = tid & 31;
    const int wid = tid >> 5;
    const int base = blockIdx.x << 8;  // * 256 rows
    const int Bm1 = B - 1;
    const int sw = (tid >> 1) & 3;     // = (row>>1)&3 (e*128 contributes 0)

    const float4* __restrict__ x4 = reinterpret_cast<const float4*>(x);
    unsigned sbase;
    asm("{ .reg .u64 t; cvta.to.shared.u64 t, %1; cvt.u32.u64 %0, t; }"
        : "=r"(sbase) : "l"(sx));

    // stage this warp's quarters q0, q1 (groups 0, 1) — no barriers at all
    STAGEW(0, 0);
    STAGEW(1, 1);

    // accumulators start at bias (from constant bank)
    long long acc[2][10];
#pragma unroll
    for (int p = 0; p < 10; ++p) {
        const longlong2 bb = c_blob[320 + (p >> 1)];   // bias floats 1280+
        const long long b = (p & 1) ? bb.y : bb.x;
        acc[0][p] = b;
        acc[1][p] = b;
    }

    // 2-buffer ping-pong; buffer reuse is thread-local and program-ordered.
    CP_WAIT(1); __syncwarp(); COMPUTE(0, 0);  // q0 landed
    STAGEW(2, 0);
    CP_WAIT(1); __syncwarp(); COMPUTE(1, 1);  // q1 landed
    STAGEW(3, 1);
    CP_WAIT(1); __syncwarp(); COMPUTE(2, 0);  // q2 landed
    CP_WAIT(0); __syncwarp(); COMPUTE(3, 1);  // q3 landed

    // epilogue (c0 from constant bank; no barriers, no L1 loads)
    long long c0p[5];
#pragma unroll
    for (int p = 0; p < 5; ++p) {
        const longlong2 cc = c_blob[325 + (p >> 1)];   // c0 floats 1300+
        c0p[p] = (p & 1) ? cc.y : cc.x;
    }
#pragma unroll
    for (int e = 0; e < 2; ++e) {
        const int row = base + (e << 7) + tid;
        if (row < B) {
            float v[10];
#pragma unroll
            for (int p = 0; p < 5; ++p) {
                long long t1, t2, s;
                MUL2(t1, acc[e][p], acc[e][p]);
                MUL2(t2, acc[e][5 + p], acc[e][5 + p]);
                ADD2(s, t1, t2);
                ADD2(s, s, c0p[p]);
                float s0, s1;
                UNPACK2(s0, s1, s);
#pragma unroll
                for (int h = 0; h < 2; ++h) {
                    float nm = fmaxf((h == 0) ? s0 : s1, 0.0f);
                    const float big = __logf(1.0f + nm);
                    const float small =
                        nm * fmaf(nm, fmaf(nm, 0.33333333f, -0.5f), 1.0f);
                    v[2 * p + h] = (nm < 0.03125f) ? small : big;
                }
            }
            float2* op = reinterpret_cast<float2*>(out + (size_t)row * 10);
#pragma unroll
            for (int j = 0; j < 5; ++j)
                op[j] = make_float2(v[2 * j], v[2 * j + 1]);
        }
    }
}

extern "C" void kernel_launch(void* const* d_in, const int* in_sizes, int n_in,
                              void* d_out, int out_size) {
    const float* x = (const float*)d_in[0];
    const int B = in_sizes[0] / 64;
    const int ntiles = (B + 255) >> 8;

    static void* g_blob_addr = nullptr;
    if (!g_blob_addr) {
        cudaFuncSetAttribute(cvqnn_main,
                             cudaFuncAttributeMaxDynamicSharedMemorySize,
                             SMEM_BYTES);
        cudaGetSymbolAddress(&g_blob_addr, g_blob);
    }

    setup_kernel<<<1, 128>>>(
        (const float*)d_in[1], (const float*)d_in[2],
        (const float*)d_in[3], (const float*)d_in[4],
        (const float*)d_in[5], (const float*)d_in[6],
        (const float*)d_in[7], (const float*)d_in[8]);

    cudaMemcpyToSymbolAsync(c_blob, g_blob_addr, 1312 * sizeof(float), 0,
                            cudaMemcpyDeviceToDevice, 0);

    cvqnn_main<<<ntiles, 128, SMEM_BYTES>>>(x, (float*)d_out, B);
}